// round 2
// baseline (speedup 1.0000x reference)
#include <cuda_runtime.h>
#include <cuda_bf16.h>
#include <mma.h>

using namespace nvcuda;

#define Bsz   2
#define Cdim  192
#define Hdim  256
#define Wdim  256
#define HW    65536
#define CHW   12582912
#define NHEAD 6
#define HD    32
#define NTOK  131072
#define C3    576
#define HID   384
#define NWIN  2048

// ---------------- scratch (device globals; no allocation allowed) ----------------
__device__ __nv_bfloat16 g_roll[(size_t)Bsz*CHW];
__device__ __nv_bfloat16 g_win[(size_t)NTOK*Cdim];
__device__ __nv_bfloat16 g_qkv[(size_t)NTOK*C3];
__device__ __nv_bfloat16 g_attnout[(size_t)NTOK*Cdim];
__device__ __nv_bfloat16 g_projout[(size_t)NTOK*Cdim];
__device__ __nv_bfloat16 g_yattn[(size_t)Bsz*CHW];
__device__ float         g_gap[Bsz*Cdim];
__device__ float         g_s[Bsz*Cdim];
__device__ float         g_x1[(size_t)Bsz*CHW];
__device__ __nv_bfloat16 g_t[(size_t)NTOK*Cdim];
__device__ __nv_bfloat16 g_h[(size_t)NTOK*HID];
__device__ float         g_y2[(size_t)NTOK*Cdim];
__device__ __nv_bfloat16 g_wqkv[Cdim*C3];
__device__ float         g_bqkv[C3];
__device__ __nv_bfloat16 g_wproj[Cdim*Cdim];
__device__ __nv_bfloat16 g_wfc1[Cdim*HID];
__device__ __nv_bfloat16 g_wfc2[HID*Cdim];

// ---------------- weight conversion (scale folded into q columns) ----------------
__global__ void k_conv_qkv(const float* __restrict__ w, const float* __restrict__ b){
    int i = blockIdx.x*256 + threadIdx.x;
    const float sc = 0.17677669529663687f; // 32^-0.5
    if (i < Cdim*C3){
        int o = i % C3;
        float f = w[i];
        if (o < Cdim) f *= sc;
        g_wqkv[i] = __float2bfloat16(f);
    }
    if (i < C3){
        float f = b[i];
        if (i < Cdim) f *= sc;
        g_bqkv[i] = f;
    }
}
__global__ void k_conv_proj(const float* __restrict__ w){
    int i = blockIdx.x*256+threadIdx.x; if(i<Cdim*Cdim) g_wproj[i]=__float2bfloat16(w[i]);
}
__global__ void k_conv_fc1(const float* __restrict__ w){
    int i = blockIdx.x*256+threadIdx.x; if(i<Cdim*HID) g_wfc1[i]=__float2bfloat16(w[i]);
}
__global__ void k_conv_fc2(const float* __restrict__ w){
    int i = blockIdx.x*256+threadIdx.x; if(i<HID*Cdim) g_wfc2[i]=__float2bfloat16(w[i]);
}

// ---------------- norm1 (over C per pixel) fused with the "buggy" flat roll ----------------
// source flat f = c*HW + h*W + w  reinterpreted as (i,j,k) with f = i*49152 + j*192 + k;
// value goes to rolled position ((i-4)&255, (j-4)&255, k).
__global__ void k_norm1_roll(const float* __restrict__ x,
                             const float* __restrict__ nw, const float* __restrict__ nb){
    __shared__ float tile[Cdim][33];
    __shared__ float red1[8][32], red2[8][32];
    __shared__ float s_mu[32], s_ri[32];
    __shared__ float s_w[Cdim], s_b[Cdim];
    int b = blockIdx.y;
    int p0 = blockIdx.x * 32;
    const float* xb = x + (size_t)b*CHW;
    int tid = threadIdx.x;
    if (tid < Cdim){ s_w[tid]=nw[tid]; s_b[tid]=nb[tid]; }
    #pragma unroll
    for (int it=0; it<24; it++){
        int idx = it*256+tid;
        int c = idx>>5, p = idx&31;
        tile[c][p] = xb[(size_t)c*HW + p0 + p];
    }
    __syncthreads();
    int p = tid&31, g = tid>>5;
    float sum=0.f, sq=0.f;
    for (int c=g; c<Cdim; c+=8){ float v=tile[c][p]; sum+=v; sq+=v*v; }
    red1[g][p]=sum; red2[g][p]=sq;
    __syncthreads();
    if (g==0){
        float s=0.f,q=0.f;
        #pragma unroll
        for (int k=0;k<8;k++){ s+=red1[k][p]; q+=red2[k][p]; }
        float mu = s*(1.f/Cdim);
        float var = q*(1.f/Cdim) - mu*mu;
        s_mu[p]=mu; s_ri[p]=rsqrtf(var+1e-6f);
    }
    __syncthreads();
    __nv_bfloat16* rb = g_roll + (size_t)b*CHW;
    #pragma unroll
    for (int it=0; it<24; it++){
        int idx = it*256+tid;
        int c = idx>>5, pp = idx&31;
        float v = (tile[c][pp]-s_mu[pp])*s_ri[pp]*s_w[c]+s_b[c];
        int f = c*HW + p0 + pp;
        int i = f/49152; int r = f - i*49152; int j = r/192; int k = r - j*192;
        int t = ((i-4)&255)*49152 + ((j-4)&255)*192 + k;
        rb[t] = __float2bfloat16(v);
    }
}

// ---------------- window partition: rolled BCHW -> (win, n, c) tokens ----------------
__global__ void k_win_gather(){
    __shared__ __nv_bfloat16 s[96][66];
    int wi = blockIdx.x; int tid = threadIdx.x;
    int b = wi>>10, gh=(wi&1023)>>5, gw=wi&31;
    const __nv_bfloat16* rb = g_roll + (size_t)b*CHW;
    size_t base = (size_t)(gh*8)*256 + gw*8;
    for (int chunk=0; chunk<2; chunk++){
        int c0 = chunk*96;
        #pragma unroll
        for (int it=0; it<24; it++){
            int idx = it*256+tid;
            int cl = idx>>6, n = idx&63;
            s[cl][n] = rb[(size_t)(c0+cl)*HW + base + (n>>3)*256 + (n&7)];
        }
        __syncthreads();
        #pragma unroll
        for (int it=0; it<24; it++){
            int idx = it*256+tid;
            int n = idx/96, cl = idx%96;
            g_win[((size_t)wi*64+n)*Cdim + c0 + cl] = s[cl][n];
        }
        __syncthreads();
    }
}

// ---------------- generic bf16 WMMA GEMM core (64x64 tile, 4 warps) ----------------
// MODE 0: bf16 out, 1: bf16 out + exact gelu, 2: f32 out
template<int MODE>
__device__ __forceinline__ void gemm_core(const __nv_bfloat16* __restrict__ A,
                                          const __nv_bfloat16* __restrict__ Bm,
                                          const float* __restrict__ bias,
                                          float* __restrict__ outF,
                                          __nv_bfloat16* __restrict__ outH,
                                          int N, int K){
    __shared__ __align__(16) __nv_bfloat16 As[64][40];
    __shared__ __align__(16) __nv_bfloat16 Bs[32][72];
    __shared__ float Cs[64][68];
    int tid = threadIdx.x;
    int m0 = blockIdx.x*64;
    int n0 = blockIdx.y*64;
    int warp = tid>>5;
    int wr = warp>>1, wc = warp&1;
    wmma::fragment<wmma::accumulator,16,16,16,float> acc[2][2];
    #pragma unroll
    for (int i=0;i<2;i++)
        #pragma unroll
        for(int j=0;j<2;j++) wmma::fill_fragment(acc[i][j], 0.f);
    for (int k0=0;k0<K;k0+=32){
        #pragma unroll
        for (int it=0; it<4; it++){
            int q = it*128+tid;
            int r = q>>3, c4 = q&7;
            *(uint2*)&As[r][c4*4] = *(const uint2*)&A[(size_t)(m0+r)*K + k0 + c4*4];
            int r2 = q>>4, c42 = q&15;
            *(uint2*)&Bs[r2][c42*4] = *(const uint2*)&Bm[(size_t)(k0+r2)*N + n0 + c42*4];
        }
        __syncthreads();
        #pragma unroll
        for (int kk=0; kk<32; kk+=16){
            wmma::fragment<wmma::matrix_a,16,16,16,__nv_bfloat16,wmma::row_major> af[2];
            wmma::fragment<wmma::matrix_b,16,16,16,__nv_bfloat16,wmma::row_major> bfr[2];
            #pragma unroll
            for (int i=0;i<2;i++) wmma::load_matrix_sync(af[i], &As[wr*32+i*16][kk], 40);
            #pragma unroll
            for (int j=0;j<2;j++) wmma::load_matrix_sync(bfr[j], &Bs[kk][wc*32+j*16], 72);
            #pragma unroll
            for (int i=0;i<2;i++)
                #pragma unroll
                for (int j=0;j<2;j++)
                    wmma::mma_sync(acc[i][j], af[i], bfr[j], acc[i][j]);
        }
        __syncthreads();
    }
    #pragma unroll
    for (int i=0;i<2;i++)
        #pragma unroll
        for(int j=0;j<2;j++)
            wmma::store_matrix_sync(&Cs[wr*32+i*16][wc*32+j*16], acc[i][j], 68, wmma::mem_row_major);
    __syncthreads();
    #pragma unroll
    for (int it=0; it<32; it++){
        int q = it*128+tid;
        int r = q>>6, c = q&63;
        float v = Cs[r][c] + bias[n0+c];
        if (MODE==1) v = 0.5f*v*(1.f+erff(v*0.70710678118654752f));
        size_t oi = (size_t)(m0+r)*N + n0 + c;
        if (MODE==2) outF[oi] = v;
        else         outH[oi] = __float2bfloat16(v);
    }
}

__global__ void k_gemm_qkv (){                           gemm_core<0>(g_win,     g_wqkv, g_bqkv, nullptr, g_qkv,     C3,   Cdim); }
__global__ void k_gemm_proj(const float* __restrict__ b){ gemm_core<0>(g_attnout, g_wproj, b,     nullptr, g_projout, Cdim, Cdim); }
__global__ void k_gemm_fc1 (const float* __restrict__ b){ gemm_core<1>(g_t,       g_wfc1,  b,     nullptr, g_h,       HID,  Cdim); }
__global__ void k_gemm_fc2 (const float* __restrict__ b){ gemm_core<2>(g_h,       g_wfc2,  b,     g_y2,    nullptr,   Cdim, HID ); }

// ---------------- fused window attention: one block per (window, head) ----------------
__global__ void k_attn(const float* __restrict__ rpb){
    __shared__ float qs[64][33], ks[64][33], vs[64][33];
    __shared__ float S[64][65];
    __shared__ float s_rpb[225];
    __shared__ int   s_cls[64];
    __shared__ float red[64][2];
    int wi = blockIdx.x, h = blockIdx.y;
    int tid = threadIdx.x;
    int gh = (wi & 1023) >> 5, gw = wi & 31;
    const __nv_bfloat16* qkvb = g_qkv + (size_t)wi*64*C3;
    #pragma unroll
    for (int it=0; it<16; it++){
        int idx = it*128+tid;
        int n = idx>>5, d = idx&31;
        size_t tb = (size_t)n*C3 + h*HD + d;
        qs[n][d] = __bfloat162float(qkvb[tb]);
        ks[n][d] = __bfloat162float(qkvb[tb+Cdim]);
        vs[n][d] = __bfloat162float(qkvb[tb+2*Cdim]);
    }
    for (int i=tid; i<225; i+=128) s_rpb[i] = rpb[i*NHEAD + h];
    if (tid < 64){
        int i = tid>>3, j = tid&7;
        int hg = gh*8+i, wg = gw*8+j;
        int rh = hg < 248 ? 0 : (hg < 252 ? 1 : 2);
        int rw = wg < 248 ? 0 : (wg < 252 ? 1 : 2);
        s_cls[tid] = rh*3+rw;
    }
    __syncthreads();
    int n = tid>>1, m0 = (tid&1)*32;
    int ni = n>>3, nj = n&7;
    int cn = s_cls[n];
    #pragma unroll 4
    for (int mi=0; mi<32; mi++){
        int m = m0+mi;
        float a = 0.f;
        #pragma unroll
        for (int d=0; d<32; d++) a += qs[n][d]*ks[m][d];
        a += s_rpb[(ni-(m>>3)+7)*15 + (nj-(m&7)+7)];
        if (cn != s_cls[m]) a -= 100.f;
        S[n][m] = a;
    }
    __syncthreads();
    float mx = -1e30f;
    #pragma unroll 8
    for (int mi=0; mi<32; mi++) mx = fmaxf(mx, S[n][m0+mi]);
    red[n][tid&1] = mx; __syncthreads();
    mx = fmaxf(red[n][0], red[n][1]); __syncthreads();
    float sm = 0.f;
    #pragma unroll 8
    for (int mi=0; mi<32; mi++){ float e = __expf(S[n][m0+mi]-mx); S[n][m0+mi]=e; sm+=e; }
    red[n][tid&1]=sm; __syncthreads();
    sm = red[n][0]+red[n][1];
    float inv = 1.f/sm;
    #pragma unroll 8
    for (int mi=0; mi<32; mi++) S[n][m0+mi] *= inv;
    __syncthreads();
    #pragma unroll
    for (int t=0; t<16; t++){
        int e = tid*16+t;
        int nn = e>>5, d = e&31;
        float a=0.f;
        #pragma unroll 8
        for (int m=0; m<64; m++) a += S[nn][m]*vs[m][d];
        g_attnout[((size_t)wi*64+nn)*Cdim + h*HD + d] = __float2bfloat16(a);
    }
}

// ---------------- window reverse: (win,n,c) tokens -> BCHW (reference does NOT un-roll) ----------------
__global__ void k_win_rev(){
    __shared__ __nv_bfloat16 s[96][66];
    int wi = blockIdx.x; int tid=threadIdx.x;
    int b = wi>>10, gh=(wi&1023)>>5, gw=wi&31;
    __nv_bfloat16* yb = g_yattn + (size_t)b*CHW;
    size_t base = (size_t)(gh*8)*256 + gw*8;
    for (int chunk=0; chunk<2; chunk++){
        int c0 = chunk*96;
        #pragma unroll
        for (int it=0; it<24; it++){
            int idx = it*256+tid;
            int n = idx/96, cl = idx%96;
            s[cl][n] = g_projout[((size_t)wi*64+n)*Cdim + c0+cl];
        }
        __syncthreads();
        #pragma unroll
        for (int it=0; it<24; it++){
            int idx = it*256+tid;
            int cl = idx>>6, n = idx&63;
            yb[(size_t)(c0+cl)*HW + base + (n>>3)*256 + (n&7)] = s[cl][n];
        }
        __syncthreads();
    }
}

// ---------------- channel attention ----------------
__global__ void k_gap(){
    int bc = blockIdx.x; int tid=threadIdx.x;
    const __nv_bfloat16* p = g_yattn + (size_t)bc*HW;
    float s=0.f;
    for (int i=tid; i<HW; i+=256) s += __bfloat162float(p[i]);
    __shared__ float r[8];
    #pragma unroll
    for (int o=16;o>0;o>>=1) s += __shfl_down_sync(0xffffffffu, s, o);
    if ((tid&31)==0) r[tid>>5]=s;
    __syncthreads();
    if (tid==0){ float t=0.f; for(int k=0;k<8;k++) t+=r[k]; g_gap[bc]=t*(1.f/HW); }
}

__global__ void k_s(const float* __restrict__ caw, const float* __restrict__ cab){
    __shared__ float gg[Bsz*Cdim];
    int tid = threadIdx.x;
    if (tid < Bsz*Cdim) gg[tid] = g_gap[tid];
    __syncthreads();
    if (tid < Bsz*Cdim){
        int b = tid/Cdim, o = tid%Cdim;
        float acc = cab[o];
        for (int c=0;c<Cdim;c++) acc += gg[b*Cdim+c]*caw[o*Cdim+c];
        g_s[tid] = acc;
    }
}

// ---------------- x1 = x + yattn*s, norm2, emit BHWC tokens for MLP ----------------
__global__ void k_addnorm2(const float* __restrict__ x,
                           const float* __restrict__ nw, const float* __restrict__ nb){
    __shared__ float tile[Cdim][33];
    __shared__ float red1[8][32], red2[8][32];
    __shared__ float s_mu[32], s_ri[32];
    __shared__ float s_w[Cdim], s_b[Cdim], s_sc[Cdim];
    int b = blockIdx.y;
    int p0 = blockIdx.x*32;
    int tid = threadIdx.x;
    if (tid < Cdim){ s_w[tid]=nw[tid]; s_b[tid]=nb[tid]; s_sc[tid]=g_s[b*Cdim+tid]; }
    __syncthreads();
    const float* xb = x + (size_t)b*CHW;
    const __nv_bfloat16* yb = g_yattn + (size_t)b*CHW;
    float* x1b = g_x1 + (size_t)b*CHW;
    #pragma unroll
    for (int it=0; it<24; it++){
        int idx = it*256+tid;
        int c = idx>>5, p = idx&31;
        size_t off = (size_t)c*HW + p0+p;
        float v = xb[off] + __bfloat162float(yb[off])*s_sc[c];
        tile[c][p]=v;
        x1b[off]=v;
    }
    __syncthreads();
    int p = tid&31, g = tid>>5;
    float sum=0.f, sq=0.f;
    for (int c=g; c<Cdim; c+=8){ float v=tile[c][p]; sum+=v; sq+=v*v; }
    red1[g][p]=sum; red2[g][p]=sq;
    __syncthreads();
    if (g==0){
        float s=0.f,q=0.f;
        #pragma unroll
        for (int k=0;k<8;k++){ s+=red1[k][p]; q+=red2[k][p]; }
        float mu = s*(1.f/Cdim);
        float var = q*(1.f/Cdim) - mu*mu;
        s_mu[p]=mu; s_ri[p]=rsqrtf(var+1e-6f);
    }
    __syncthreads();
    #pragma unroll
    for (int it=0; it<24; it++){
        int idx = it*256+tid;
        int pp = idx/192, c = idx%192;
        float v = (tile[c][pp]-s_mu[pp])*s_ri[pp]*s_w[c]+s_b[c];
        g_t[((size_t)b*HW + p0+pp)*Cdim + c] = __float2bfloat16(v);
    }
}

// ---------------- final: out = x1 + y2 (BHWC tokens -> BCHW via smem transpose) ----------------
__global__ void k_final(float* __restrict__ out){
    __shared__ float s[Cdim][33];
    int b = blockIdx.y; int p0 = blockIdx.x*32; int tid=threadIdx.x;
    #pragma unroll
    for (int it=0; it<24; it++){
        int idx = it*256+tid;
        int p = idx/192, c = idx%192;
        s[c][p] = g_y2[((size_t)b*HW+p0+p)*Cdim + c];
    }
    __syncthreads();
    #pragma unroll
    for (int it=0; it<24; it++){
        int idx = it*256+tid;
        int c = idx>>5, p = idx&31;
        size_t off = (size_t)b*CHW + (size_t)c*HW + p0+p;
        out[off] = g_x1[off] + s[c][p];
    }
}

// ---------------- launch ----------------
extern "C" void kernel_launch(void* const* d_in, const int* in_sizes, int n_in,
                              void* d_out, int out_size){
    const float* x    = (const float*)d_in[0];
    const float* n1w  = (const float*)d_in[1];
    const float* n1b  = (const float*)d_in[2];
    const float* qkvw = (const float*)d_in[3];
    const float* qkvb = (const float*)d_in[4];
    const float* projb= (const float*)d_in[6];
    const float* rpb  = (const float*)d_in[7];
    const float* caw  = (const float*)d_in[8];
    const float* cab  = (const float*)d_in[9];
    const float* n2w  = (const float*)d_in[10];
    const float* n2b  = (const float*)d_in[11];
    const float* fc1w = (const float*)d_in[12];
    const float* fc1b = (const float*)d_in[13];
    const float* fc2w = (const float*)d_in[14];
    const float* fc2b = (const float*)d_in[15];
    const float* projw= (const float*)d_in[5];
    float* out = (float*)d_out;

    k_conv_qkv <<<(Cdim*C3+255)/256, 256>>>(qkvw, qkvb);
    k_conv_proj<<<(Cdim*Cdim+255)/256,256>>>(projw);
    k_conv_fc1 <<<(Cdim*HID+255)/256, 256>>>(fc1w);
    k_conv_fc2 <<<(HID*Cdim+255)/256, 256>>>(fc2w);

    k_norm1_roll<<<dim3(HW/32, Bsz), 256>>>(x, n1w, n1b);
    k_win_gather<<<NWIN, 256>>>();
    k_gemm_qkv  <<<dim3(NTOK/64, C3/64),  128>>>();
    k_attn      <<<dim3(NWIN, NHEAD),     128>>>(rpb);
    k_gemm_proj <<<dim3(NTOK/64, Cdim/64),128>>>(projb);
    k_win_rev   <<<NWIN, 256>>>();
    k_gap       <<<Bsz*Cdim, 256>>>();
    k_s         <<<1, 384>>>(caw, cab);
    k_addnorm2  <<<dim3(HW/32, Bsz), 256>>>(x, n2w, n2b);
    k_gemm_fc1  <<<dim3(NTOK/64, HID/64), 128>>>(fc1b);
    k_gemm_fc2  <<<dim3(NTOK/64, Cdim/64),128>>>(fc2b);
    k_final     <<<dim3(HW/32, Bsz), 256>>>(out);
}

// round 6
// speedup vs baseline: 1.3043x; 1.3043x over previous
#include <cuda_runtime.h>
#include <cuda_bf16.h>
#include <mma.h>

using namespace nvcuda;

#define Bsz   2
#define Cdim  192
#define Hdim  256
#define Wdim  256
#define HW    65536
#define CHW   12582912
#define NHEAD 6
#define HD    32
#define NTOK  131072
#define C3    576
#define HID   384
#define NWIN  2048

// ---------------- scratch (device globals; no allocation allowed) ----------------
__device__ __nv_bfloat16 g_roll[(size_t)Bsz*CHW];
__device__ __nv_bfloat16 g_win[(size_t)NTOK*Cdim];
__device__ __nv_bfloat16 g_qkv[(size_t)NTOK*C3];
__device__ __nv_bfloat16 g_attnout[(size_t)NTOK*Cdim];
__device__ __nv_bfloat16 g_projout[(size_t)NTOK*Cdim];
__device__ __nv_bfloat16 g_yattn[(size_t)Bsz*CHW];
__device__ float         g_gap[Bsz*Cdim];
__device__ float         g_s[Bsz*Cdim];
__device__ float         g_x1[(size_t)Bsz*CHW];
__device__ __nv_bfloat16 g_t[(size_t)NTOK*Cdim];
__device__ __nv_bfloat16 g_h[(size_t)NTOK*HID];
__device__ float         g_y2[(size_t)NTOK*Cdim];
__device__ __nv_bfloat16 g_wqkv[Cdim*C3];
__device__ float         g_bqkv[C3];
__device__ __nv_bfloat16 g_wproj[Cdim*Cdim];
__device__ __nv_bfloat16 g_wfc1[Cdim*HID];
__device__ __nv_bfloat16 g_wfc2[HID*Cdim];

// ---------------- weight conversion (scale folded into q columns) ----------------
__global__ void k_conv_qkv(const float* __restrict__ w, const float* __restrict__ b){
    int i = blockIdx.x*256 + threadIdx.x;
    const float sc = 0.17677669529663687f; // 32^-0.5
    if (i < Cdim*C3){
        int o = i % C3;
        float f = w[i];
        if (o < Cdim) f *= sc;
        g_wqkv[i] = __float2bfloat16(f);
    }
    if (i < C3){
        float f = b[i];
        if (i < Cdim) f *= sc;
        g_bqkv[i] = f;
    }
}
__global__ void k_conv_proj(const float* __restrict__ w){
    int i = blockIdx.x*256+threadIdx.x; if(i<Cdim*Cdim) g_wproj[i]=__float2bfloat16(w[i]);
}
__global__ void k_conv_fc1(const float* __restrict__ w){
    int i = blockIdx.x*256+threadIdx.x; if(i<Cdim*HID) g_wfc1[i]=__float2bfloat16(w[i]);
}
__global__ void k_conv_fc2(const float* __restrict__ w){
    int i = blockIdx.x*256+threadIdx.x; if(i<HID*Cdim) g_wfc2[i]=__float2bfloat16(w[i]);
}

// ---------------- norm1 (over C per pixel) fused with the "buggy" flat roll ----------------
__global__ void k_norm1_roll(const float* __restrict__ x,
                             const float* __restrict__ nw, const float* __restrict__ nb){
    __shared__ float tile[Cdim][33];
    __shared__ float red1[8][32], red2[8][32];
    __shared__ float s_mu[32], s_ri[32];
    __shared__ float s_w[Cdim], s_b[Cdim];
    int b = blockIdx.y;
    int p0 = blockIdx.x * 32;
    const float* xb = x + (size_t)b*CHW;
    int tid = threadIdx.x;
    if (tid < Cdim){ s_w[tid]=nw[tid]; s_b[tid]=nb[tid]; }
    #pragma unroll
    for (int it=0; it<24; it++){
        int idx = it*256+tid;
        int c = idx>>5, p = idx&31;
        tile[c][p] = xb[(size_t)c*HW + p0 + p];
    }
    __syncthreads();
    int p = tid&31, g = tid>>5;
    float sum=0.f, sq=0.f;
    for (int c=g; c<Cdim; c+=8){ float v=tile[c][p]; sum+=v; sq+=v*v; }
    red1[g][p]=sum; red2[g][p]=sq;
    __syncthreads();
    if (g==0){
        float s=0.f,q=0.f;
        #pragma unroll
        for (int k=0;k<8;k++){ s+=red1[k][p]; q+=red2[k][p]; }
        float mu = s*(1.f/Cdim);
        float var = q*(1.f/Cdim) - mu*mu;
        s_mu[p]=mu; s_ri[p]=rsqrtf(var+1e-6f);
    }
    __syncthreads();
    __nv_bfloat16* rb = g_roll + (size_t)b*CHW;
    #pragma unroll
    for (int it=0; it<24; it++){
        int idx = it*256+tid;
        int c = idx>>5, pp = idx&31;
        float v = (tile[c][pp]-s_mu[pp])*s_ri[pp]*s_w[c]+s_b[c];
        int f = c*HW + p0 + pp;
        int i = f/49152; int r = f - i*49152; int j = r/192; int k = r - j*192;
        int t = ((i-4)&255)*49152 + ((j-4)&255)*192 + k;
        rb[t] = __float2bfloat16(v);
    }
}

// ---------------- window partition: rolled BCHW -> (win, n, c) tokens ----------------
__global__ void k_win_gather(){
    __shared__ __nv_bfloat16 s[96][66];
    int wi = blockIdx.x; int tid = threadIdx.x;
    int b = wi>>10, gh=(wi&1023)>>5, gw=wi&31;
    const __nv_bfloat16* rb = g_roll + (size_t)b*CHW;
    size_t base = (size_t)(gh*8)*256 + gw*8;
    for (int chunk=0; chunk<2; chunk++){
        int c0 = chunk*96;
        #pragma unroll
        for (int it=0; it<24; it++){
            int idx = it*256+tid;
            int cl = idx>>6, n = idx&63;
            s[cl][n] = rb[(size_t)(c0+cl)*HW + base + (n>>3)*256 + (n&7)];
        }
        __syncthreads();
        #pragma unroll
        for (int it=0; it<24; it++){
            int idx = it*256+tid;
            int n = idx/96, cl = idx%96;
            g_win[((size_t)wi*64+n)*Cdim + c0 + cl] = s[cl][n];
        }
        __syncthreads();
    }
}

// ---------------- high-throughput WMMA GEMM: 128x64 tile, resident B, double-buffered A --------
// MODE 0: bf16 out, 1: bf16 out + exact gelu, 2: f32 out
template<int K, int N, int MODE>
__device__ __forceinline__ void gemm_body(const __nv_bfloat16* __restrict__ A,
                                          const __nv_bfloat16* __restrict__ Bm,
                                          const float* __restrict__ bias,
                                          float* __restrict__ outF,
                                          __nv_bfloat16* __restrict__ outH){
    extern __shared__ __align__(16) char sm[];
    __nv_bfloat16* Bs = (__nv_bfloat16*)sm;                       // [K][80]
    __nv_bfloat16* As = (__nv_bfloat16*)(sm + (size_t)K*80*2);    // [2][128][80]
    float*         Cs = (float*)(sm + (size_t)K*80*2);            // [128][68] (aliases As)
    const int tid = threadIdx.x;
    const int m0 = blockIdx.x*128, n0 = blockIdx.y*64;
    const int warp = tid>>5, wr = warp>>1, wc = warp&1;

    // load full B slice (K x 64) once
    #pragma unroll
    for (int it=0; it<K/32; it++){
        int idx = it*256+tid;
        int row = idx>>3, u = idx&7;
        *(uint4*)&Bs[row*80 + u*8] = *(const uint4*)&Bm[(size_t)row*N + n0 + u*8];
    }
    // A chunk loader (64-wide K chunks)
    auto loadA = [&](int c, int buf){
        #pragma unroll
        for (int it=0; it<4; it++){
            int idx = it*256+tid;
            int row = idx>>3, u = idx&7;
            *(uint4*)&As[(size_t)(buf*128+row)*80 + u*8] =
                *(const uint4*)&A[(size_t)(m0+row)*K + c*64 + u*8];
        }
    };
    loadA(0,0);
    wmma::fragment<wmma::accumulator,16,16,16,float> acc[2][2];
    #pragma unroll
    for (int i=0;i<2;i++)
        #pragma unroll
        for (int j=0;j<2;j++) wmma::fill_fragment(acc[i][j], 0.f);
    __syncthreads();

    constexpr int NC = K/64;
    #pragma unroll
    for (int c=0;c<NC;c++){
        if (c+1 < NC) loadA(c+1, (c+1)&1);
        int buf = c&1;
        #pragma unroll
        for (int kk=0;kk<64;kk+=16){
            wmma::fragment<wmma::matrix_a,16,16,16,__nv_bfloat16,wmma::row_major> af[2];
            wmma::fragment<wmma::matrix_b,16,16,16,__nv_bfloat16,wmma::row_major> bf[2];
            #pragma unroll
            for (int i=0;i<2;i++) wmma::load_matrix_sync(af[i], &As[(size_t)(buf*128+wr*32+i*16)*80 + kk], 80);
            #pragma unroll
            for (int j=0;j<2;j++) wmma::load_matrix_sync(bf[j], &Bs[(size_t)(c*64+kk)*80 + wc*32+j*16], 80);
            #pragma unroll
            for (int i=0;i<2;i++)
                #pragma unroll
                for (int j=0;j<2;j++)
                    wmma::mma_sync(acc[i][j], af[i], bf[j], acc[i][j]);
        }
        __syncthreads();
    }
    #pragma unroll
    for (int i=0;i<2;i++)
        #pragma unroll
        for (int j=0;j<2;j++)
            wmma::store_matrix_sync(&Cs[(size_t)(wr*32+i*16)*68 + wc*32+j*16], acc[i][j], 68, wmma::mem_row_major);
    __syncthreads();
    #pragma unroll
    for (int it=0; it<32; it++){
        int idx = it*256+tid;
        int r = idx>>6, cc = idx&63;
        float v = Cs[(size_t)r*68+cc] + bias[n0+cc];
        if (MODE==1) v = 0.5f*v*(1.f+erff(v*0.70710678118654752f));
        size_t oi = (size_t)(m0+r)*N + n0 + cc;
        if (MODE==2) outF[oi] = v;
        else         outH[oi] = __float2bfloat16(v);
    }
}

__global__ void __launch_bounds__(256) k_gemm_qkv(){
    gemm_body<Cdim,C3,0>(g_win, g_wqkv, g_bqkv, nullptr, g_qkv);
}
__global__ void __launch_bounds__(256) k_gemm_proj(const float* __restrict__ b){
    gemm_body<Cdim,Cdim,0>(g_attnout, g_wproj, b, nullptr, g_projout);
}
__global__ void __launch_bounds__(256) k_gemm_fc1(const float* __restrict__ b){
    gemm_body<Cdim,HID,1>(g_t, g_wfc1, b, nullptr, g_h);
}
__global__ void __launch_bounds__(256) k_gemm_fc2(const float* __restrict__ b){
    gemm_body<HID,Cdim,2>(g_h, g_wfc2, b, g_y2, nullptr);
}

// ---------------- fused window attention, WMMA: one block per window, all 6 heads -----------
#define LDQ 584
__global__ void __launch_bounds__(256) k_attn(const float* __restrict__ rpb){
    extern __shared__ __align__(16) char sm[];
    __nv_bfloat16* sQ   = (__nv_bfloat16*)sm;                     // [64][584]
    float*         sS   = (float*)(sm + 64*LDQ*2);                // [8][16*68]
    __nv_bfloat16* sP   = (__nv_bfloat16*)(sm + 64*LDQ*2 + 8*16*68*4); // [8][16*72]
    float*         sRpb = (float*)(sm + 64*LDQ*2 + 8*16*68*4 + 8*16*72*2); // [6*225]
    int*           sCls = (int*)(sm + 64*LDQ*2 + 8*16*68*4 + 8*16*72*2 + 6*225*4); // [64]
    int wi = blockIdx.x;
    int tid = threadIdx.x, warp = tid>>5, lane = tid&31;
    int gh = (wi & 1023) >> 5, gw = wi & 31;

    // load whole window's qkv (64 x 576)
    const __nv_bfloat16* qkvb = g_qkv + (size_t)wi*64*C3;
    #pragma unroll
    for (int it=0; it<18; it++){
        int idx = it*256+tid;
        int row = idx/72, u = idx%72;
        *(uint4*)&sQ[row*LDQ + u*8] = *(const uint4*)&qkvb[(size_t)row*C3 + u*8];
    }
    for (int i=tid; i<NHEAD*225; i+=256){
        int h = i/225, p = i%225;
        sRpb[h*225+p] = rpb[p*NHEAD + h];
    }
    if (tid < 64){
        int i = tid>>3, j = tid&7;
        int hg = gh*8+i, wg = gw*8+j;
        int rh = hg < 248 ? 0 : (hg < 252 ? 1 : 2);
        int rw = wg < 248 ? 0 : (wg < 252 ? 1 : 2);
        sCls[tid] = rh*3+rw;
    }
    __syncthreads();

    #pragma unroll
    for (int r=0; r<3; r++){
        int task = warp + 8*r;            // 0..23
        int h = task>>2, strip = task&3, n0 = strip*16;
        float*         Sw = sS + warp*16*68;
        __nv_bfloat16* Pw = sP + warp*16*72;
        // ---- S = Q Kt (16x64) ----
        wmma::fragment<wmma::accumulator,16,16,16,float> acc[4];
        #pragma unroll
        for (int j=0;j<4;j++) wmma::fill_fragment(acc[j], 0.f);
        #pragma unroll
        for (int kk=0; kk<32; kk+=16){
            wmma::fragment<wmma::matrix_a,16,16,16,__nv_bfloat16,wmma::row_major> aq;
            wmma::load_matrix_sync(aq, &sQ[(size_t)n0*LDQ + h*HD + kk], LDQ);
            #pragma unroll
            for (int j=0;j<4;j++){
                wmma::fragment<wmma::matrix_b,16,16,16,__nv_bfloat16,wmma::col_major> bk;
                wmma::load_matrix_sync(bk, &sQ[(size_t)(j*16)*LDQ + Cdim + h*HD + kk], LDQ);
                wmma::mma_sync(acc[j], aq, bk, acc[j]);
            }
        }
        #pragma unroll
        for (int j=0;j<4;j++)
            wmma::store_matrix_sync(&Sw[j*16], acc[j], 68, wmma::mem_row_major);
        __syncwarp();
        // ---- softmax with rpb bias + shift mask (each lane: one row half) ----
        {
            int row = lane>>1, half = (lane&1)*32;
            int n = n0+row, ni = n>>3, nj = n&7;
            int cn = sCls[n];
            const float* rh = sRpb + h*225;
            float e[32]; float mx = -1e30f;
            #pragma unroll
            for (int c=0;c<32;c++){
                int m = half+c;
                float v = Sw[row*68+m] + rh[(ni-(m>>3)+7)*15 + (nj-(m&7)+7)];
                if (cn != sCls[m]) v -= 100.f;
                e[c]=v; mx = fmaxf(mx, v);
            }
            mx = fmaxf(mx, __shfl_xor_sync(0xffffffffu, mx, 1));
            float sum = 0.f;
            #pragma unroll
            for (int c=0;c<32;c++){ e[c] = __expf(e[c]-mx); sum += e[c]; }
            sum += __shfl_xor_sync(0xffffffffu, sum, 1);
            float inv = 1.f/sum;
            #pragma unroll
            for (int c=0;c<32;c++) Pw[row*72+half+c] = __float2bfloat16(e[c]*inv);
        }
        __syncwarp();
        // ---- out = P V (16x32) ----
        wmma::fragment<wmma::accumulator,16,16,16,float> acc2[2];
        #pragma unroll
        for (int j=0;j<2;j++) wmma::fill_fragment(acc2[j], 0.f);
        #pragma unroll
        for (int k4=0;k4<4;k4++){
            wmma::fragment<wmma::matrix_a,16,16,16,__nv_bfloat16,wmma::row_major> ap;
            wmma::load_matrix_sync(ap, &Pw[k4*16], 72);
            #pragma unroll
            for (int j=0;j<2;j++){
                wmma::fragment<wmma::matrix_b,16,16,16,__nv_bfloat16,wmma::row_major> bv;
                wmma::load_matrix_sync(bv, &sQ[(size_t)(k4*16)*LDQ + 2*Cdim + h*HD + j*16], LDQ);
                wmma::mma_sync(acc2[j], ap, bv, acc2[j]);
            }
        }
        #pragma unroll
        for (int j=0;j<2;j++)
            wmma::store_matrix_sync(&Sw[j*16], acc2[j], 36, wmma::mem_row_major);
        __syncwarp();
        {
            int row = lane>>1, halfo = (lane&1)*16;
            __nv_bfloat16* op = g_attnout + ((size_t)(wi*64 + n0+row))*Cdim + h*HD + halfo;
            #pragma unroll
            for (int c=0;c<16;c++) op[c] = __float2bfloat16(Sw[row*36 + halfo + c]);
        }
        __syncwarp();
    }
}

// ---------------- window reverse: (win,n,c) tokens -> BCHW ----------------
__global__ void k_win_rev(){
    __shared__ __nv_bfloat16 s[96][66];
    int wi = blockIdx.x; int tid=threadIdx.x;
    int b = wi>>10, gh=(wi&1023)>>5, gw=wi&31;
    __nv_bfloat16* yb = g_yattn + (size_t)b*CHW;
    size_t base = (size_t)(gh*8)*256 + gw*8;
    for (int chunk=0; chunk<2; chunk++){
        int c0 = chunk*96;
        #pragma unroll
        for (int it=0; it<24; it++){
            int idx = it*256+tid;
            int n = idx/96, cl = idx%96;
            s[cl][n] = g_projout[((size_t)wi*64+n)*Cdim + c0+cl];
        }
        __syncthreads();
        #pragma unroll
        for (int it=0; it<24; it++){
            int idx = it*256+tid;
            int cl = idx>>6, n = idx&63;
            yb[(size_t)(c0+cl)*HW + base + (n>>3)*256 + (n&7)] = s[cl][n];
        }
        __syncthreads();
    }
}

// ---------------- channel attention ----------------
__global__ void k_gap(){
    int bc = blockIdx.x; int tid=threadIdx.x;
    const __nv_bfloat16* p = g_yattn + (size_t)bc*HW;
    float s=0.f;
    for (int i=tid; i<HW; i+=256) s += __bfloat162float(p[i]);
    __shared__ float r[8];
    #pragma unroll
    for (int o=16;o>0;o>>=1) s += __shfl_down_sync(0xffffffffu, s, o);
    if ((tid&31)==0) r[tid>>5]=s;
    __syncthreads();
    if (tid==0){ float t=0.f; for(int k=0;k<8;k++) t+=r[k]; g_gap[bc]=t*(1.f/HW); }
}

__global__ void k_s(const float* __restrict__ caw, const float* __restrict__ cab){
    __shared__ float gg[Bsz*Cdim];
    int tid = threadIdx.x;
    if (tid < Bsz*Cdim) gg[tid] = g_gap[tid];
    __syncthreads();
    if (tid < Bsz*Cdim){
        int b = tid/Cdim, o = tid%Cdim;
        float acc = cab[o];
        for (int c=0;c<Cdim;c++) acc += gg[b*Cdim+c]*caw[o*Cdim+c];
        g_s[tid] = acc;
    }
}

// ---------------- x1 = x + yattn*s, norm2, emit BHWC tokens for MLP ----------------
__global__ void k_addnorm2(const float* __restrict__ x,
                           const float* __restrict__ nw, const float* __restrict__ nb){
    __shared__ float tile[Cdim][33];
    __shared__ float red1[8][32], red2[8][32];
    __shared__ float s_mu[32], s_ri[32];
    __shared__ float s_w[Cdim], s_b[Cdim], s_sc[Cdim];
    int b = blockIdx.y;
    int p0 = blockIdx.x*32;
    int tid = threadIdx.x;
    if (tid < Cdim){ s_w[tid]=nw[tid]; s_b[tid]=nb[tid]; s_sc[tid]=g_s[b*Cdim+tid]; }
    __syncthreads();
    const float* xb = x + (size_t)b*CHW;
    const __nv_bfloat16* yb = g_yattn + (size_t)b*CHW;
    float* x1b = g_x1 + (size_t)b*CHW;
    #pragma unroll
    for (int it=0; it<24; it++){
        int idx = it*256+tid;
        int c = idx>>5, p = idx&31;
        size_t off = (size_t)c*HW + p0+p;
        float v = xb[off] + __bfloat162float(yb[off])*s_sc[c];
        tile[c][p]=v;
        x1b[off]=v;
    }
    __syncthreads();
    int p = tid&31, g = tid>>5;
    float sum=0.f, sq=0.f;
    for (int c=g; c<Cdim; c+=8){ float v=tile[c][p]; sum+=v; sq+=v*v; }
    red1[g][p]=sum; red2[g][p]=sq;
    __syncthreads();
    if (g==0){
        float s=0.f,q=0.f;
        #pragma unroll
        for (int k=0;k<8;k++){ s+=red1[k][p]; q+=red2[k][p]; }
        float mu = s*(1.f/Cdim);
        float var = q*(1.f/Cdim) - mu*mu;
        s_mu[p]=mu; s_ri[p]=rsqrtf(var+1e-6f);
    }
    __syncthreads();
    #pragma unroll
    for (int it=0; it<24; it++){
        int idx = it*256+tid;
        int pp = idx/192, c = idx%192;
        float v = (tile[c][pp]-s_mu[pp])*s_ri[pp]*s_w[c]+s_b[c];
        g_t[((size_t)b*HW + p0+pp)*Cdim + c] = __float2bfloat16(v);
    }
}

// ---------------- final: out = x1 + y2 (BHWC tokens -> BCHW via smem transpose) ----------------
__global__ void k_final(float* __restrict__ out){
    __shared__ float s[Cdim][33];
    int b = blockIdx.y; int p0 = blockIdx.x*32; int tid=threadIdx.x;
    #pragma unroll
    for (int it=0; it<24; it++){
        int idx = it*256+tid;
        int p = idx/192, c = idx%192;
        s[c][p] = g_y2[((size_t)b*HW+p0+p)*Cdim + c];
    }
    __syncthreads();
    #pragma unroll
    for (int it=0; it<24; it++){
        int idx = it*256+tid;
        int c = idx>>5, p = idx&31;
        size_t off = (size_t)b*CHW + (size_t)c*HW + p0+p;
        out[off] = g_x1[off] + s[c][p];
    }
}

// ---------------- launch ----------------
extern "C" void kernel_launch(void* const* d_in, const int* in_sizes, int n_in,
                              void* d_out, int out_size){
    const float* x    = (const float*)d_in[0];
    const float* n1w  = (const float*)d_in[1];
    const float* n1b  = (const float*)d_in[2];
    const float* qkvw = (const float*)d_in[3];
    const float* qkvb = (const float*)d_in[4];
    const float* projw= (const float*)d_in[5];
    const float* projb= (const float*)d_in[6];
    const float* rpb  = (const float*)d_in[7];
    const float* caw  = (const float*)d_in[8];
    const float* cab  = (const float*)d_in[9];
    const float* n2w  = (const float*)d_in[10];
    const float* n2b  = (const float*)d_in[11];
    const float* fc1w = (const float*)d_in[12];
    const float* fc1b = (const float*)d_in[13];
    const float* fc2w = (const float*)d_in[14];
    const float* fc2b = (const float*)d_in[15];
    float* out = (float*)d_out;

    const int smA    = 64*LDQ*2 + 8*16*68*4 + 8*16*72*2 + 6*225*4 + 64*4; // 133656
    const int smG192 = 192*80*2 + 2*128*80*2;   // 71680
    const int smG384 = 384*80*2 + 2*128*80*2;   // 102400
    static bool attr_done = false;
    if (!attr_done){
        cudaFuncSetAttribute(k_attn,      cudaFuncAttributeMaxDynamicSharedMemorySize, smA);
        cudaFuncSetAttribute(k_gemm_qkv,  cudaFuncAttributeMaxDynamicSharedMemorySize, smG192);
        cudaFuncSetAttribute(k_gemm_proj, cudaFuncAttributeMaxDynamicSharedMemorySize, smG192);
        cudaFuncSetAttribute(k_gemm_fc1,  cudaFuncAttributeMaxDynamicSharedMemorySize, smG192);
        cudaFuncSetAttribute(k_gemm_fc2,  cudaFuncAttributeMaxDynamicSharedMemorySize, smG384);
        attr_done = true;
    }

    k_conv_qkv <<<(Cdim*C3+255)/256, 256>>>(qkvw, qkvb);
    k_conv_proj<<<(Cdim*Cdim+255)/256,256>>>(projw);
    k_conv_fc1 <<<(Cdim*HID+255)/256, 256>>>(fc1w);
    k_conv_fc2 <<<(HID*Cdim+255)/256, 256>>>(fc2w);

    k_norm1_roll<<<dim3(HW/32, Bsz), 256>>>(x, n1w, n1b);
    k_win_gather<<<NWIN, 256>>>();
    k_gemm_qkv  <<<dim3(NTOK/128, C3/64),   256, smG192>>>();
    k_attn      <<<NWIN, 256, smA>>>(rpb);
    k_gemm_proj <<<dim3(NTOK/128, Cdim/64), 256, smG192>>>(projb);
    k_win_rev   <<<NWIN, 256>>>();
    k_gap       <<<Bsz*Cdim, 256>>>();
    k_s         <<<1, 384>>>(caw, cab);
    k_addnorm2  <<<dim3(HW/32, Bsz), 256>>>(x, n2w, n2b);
    k_gemm_fc1  <<<dim3(NTOK/128, HID/64),  256, smG192>>>(fc1b);
    k_gemm_fc2  <<<dim3(NTOK/128, Cdim/64), 256, smG384>>>(fc2b);
    k_final     <<<dim3(HW/32, Bsz), 256>>>(out);
}